// round 2
// baseline (speedup 1.0000x reference)
#include <cuda_runtime.h>
#include <cuda_bf16.h>
#include <math.h>

#define N_NODES 50000
#define N_EDGES 800000
#define E2      (N_EDGES + N_NODES)   // edges + self loops = 850000
#define HEADS   4
#define DIM     128                   // HEADS * 32

// -------- persistent scratch (no allocations allowed) --------
__device__ float    g_h[N_NODES * DIM];        // 25.6 MB  projected features
__device__ float    g_as[N_NODES * HEADS];     // a_src per node/head
__device__ float    g_ad[N_NODES * HEADS];     // a_dst per node/head
__device__ unsigned g_max[N_NODES * HEADS];    // ordered-uint encoded segment max
__device__ float    g_den[N_NODES * HEADS];    // softmax denominator
__device__ float    g_eexp[E2 * HEADS];        // 13.6 MB  exp(e - max) per edge/head
__device__ int      g_is64;                    // edge_index dtype flag

// ordered-uint encoding for float atomicMax (handles negatives)
__device__ __forceinline__ unsigned fenc(float f) {
    unsigned u = __float_as_uint(f);
    return (u & 0x80000000u) ? ~u : (u | 0x80000000u);
}
__device__ __forceinline__ float fdec(unsigned e) {
    return (e & 0x80000000u) ? __uint_as_float(e & 0x7FFFFFFFu)
                             : __uint_as_float(~e);
}

// fetch (src,dst) for edge e, handling either int32 or int64 edge_index
__device__ __forceinline__ void load_edge(const void* __restrict__ ei, int e,
                                          int& src, int& dst) {
    if (e < N_EDGES) {
        if (g_is64) {
            const long long* p = (const long long*)ei;
            src = (int)p[e]; dst = (int)p[N_EDGES + e];
        } else {
            const int* p = (const int*)ei;
            src = p[e]; dst = p[N_EDGES + e];
        }
    } else {
        src = dst = e - N_EDGES;
    }
}

// ---------------- kernel D: detect edge_index dtype ----------------
// If int64 with values < 2^31, every odd 32-bit word is 0.
__global__ void k_detect(const unsigned* __restrict__ ei32) {
    if (threadIdx.x == 0) {
        int all_hi_zero = 1;
        for (int i = 0; i < 32; i++)
            if (ei32[2 * i + 1] != 0u) { all_hi_zero = 0; break; }
        g_is64 = all_hi_zero;
    }
}

// ---------------- kernel 0: init scratch + zero output ----------------
__global__ void k_init(float4* __restrict__ out4) {
    int i = blockIdx.x * blockDim.x + threadIdx.x;
    if (i < N_NODES * 32) out4[i] = make_float4(0.f, 0.f, 0.f, 0.f);
    if (i < N_NODES * HEADS) { g_max[i] = 0u; g_den[i] = 0.f; }
}

// ---------------- kernel 1: h = x @ W ; a_s, a_d fused ----------------
// one warp per node; W rows loaded as float4 (L1/L2 resident, 64 KB)
__global__ __launch_bounds__(256) void k_gemm(
    const float* __restrict__ x, const float* __restrict__ W,
    const float* __restrict__ att_s, const float* __restrict__ att_d)
{
    int warp = (blockIdx.x * blockDim.x + threadIdx.x) >> 5;
    int lane = threadIdx.x & 31;
    if (warp >= N_NODES) return;

    const float* xr = x + warp * DIM;
    float xv[4];
#pragma unroll
    for (int j = 0; j < 4; j++) xv[j] = xr[j * 32 + lane];

    float4 acc = make_float4(0.f, 0.f, 0.f, 0.f);
    const float4* W4 = (const float4*)W;
#pragma unroll 8
    for (int k = 0; k < 128; k++) {
        float xk = __shfl_sync(0xffffffffu, xv[k >> 5], k & 31);
        float4 w = W4[k * 32 + lane];
        acc.x = fmaf(xk, w.x, acc.x);
        acc.y = fmaf(xk, w.y, acc.y);
        acc.z = fmaf(xk, w.z, acc.z);
        acc.w = fmaf(xk, w.w, acc.w);
    }
    ((float4*)g_h)[warp * 32 + lane] = acc;

    // attention dot products: cols lane*4..+3 belong to head = lane/8
    int head = lane >> 3;
    int base = head * 32 + (lane & 7) * 4;
    float s = acc.x * att_s[base + 0] + acc.y * att_s[base + 1]
            + acc.z * att_s[base + 2] + acc.w * att_s[base + 3];
    float d = acc.x * att_d[base + 0] + acc.y * att_d[base + 1]
            + acc.z * att_d[base + 2] + acc.w * att_d[base + 3];
#pragma unroll
    for (int off = 4; off >= 1; off >>= 1) {
        s += __shfl_xor_sync(0xffffffffu, s, off);
        d += __shfl_xor_sync(0xffffffffu, d, off);
    }
    if ((lane & 7) == 0) {
        g_as[warp * HEADS + head] = s;
        g_ad[warp * HEADS + head] = d;
    }
}

// ---------------- kernel 2: segment max over dst ----------------
__global__ __launch_bounds__(256) void k_edge_max(const void* __restrict__ ei) {
    int e = blockIdx.x * blockDim.x + threadIdx.x;
    if (e >= E2) return;
    int src, dst;
    load_edge(ei, e, src, dst);

    float4 a = *(const float4*)(g_as + src * HEADS);
    float4 b = *(const float4*)(g_ad + dst * HEADS);
    float ev[4] = { a.x + b.x, a.y + b.y, a.z + b.z, a.w + b.w };
    unsigned* m = g_max + dst * HEADS;
#pragma unroll
    for (int h = 0; h < 4; h++) {
        float t = ev[h];
        t = (t < 0.f) ? 0.2f * t : t;           // leaky relu
        atomicMax(&m[h], fenc(t));
    }
}

// ---------------- kernel 3: e_exp + denominator ----------------
__global__ __launch_bounds__(256) void k_edge_exp(const void* __restrict__ ei) {
    int e = blockIdx.x * blockDim.x + threadIdx.x;
    if (e >= E2) return;
    int src, dst;
    load_edge(ei, e, src, dst);

    float4 a = *(const float4*)(g_as + src * HEADS);
    float4 b = *(const float4*)(g_ad + dst * HEADS);
    uint4  m = *(const uint4*)(g_max + dst * HEADS);
    float ev[4] = { a.x + b.x, a.y + b.y, a.z + b.z, a.w + b.w };
    unsigned mv[4] = { m.x, m.y, m.z, m.w };
    float ex[4];
    float* den = g_den + dst * HEADS;
#pragma unroll
    for (int h = 0; h < 4; h++) {
        float t = ev[h];
        t = (t < 0.f) ? 0.2f * t : t;
        ex[h] = __expf(t - fdec(mv[h]));
        atomicAdd(&den[h], ex[h]);
    }
    *(float4*)(g_eexp + (size_t)e * HEADS) = make_float4(ex[0], ex[1], ex[2], ex[3]);
}

// ---------------- kernel 4: aggregate messages (warp per edge) ----------------
// out[dst, :] += e_exp[e, head] * h[src, :]   (division by denom deferred)
__global__ __launch_bounds__(256) void k_edge_agg(
    const void* __restrict__ ei, float* __restrict__ out)
{
    int e = blockIdx.x * (blockDim.x >> 5) + (threadIdx.x >> 5);
    int lane = threadIdx.x & 31;
    if (e >= E2) return;
    int src, dst;
    load_edge(ei, e, src, dst);

    float w = g_eexp[(size_t)e * HEADS + (lane >> 3)];   // broadcast within 16B segment
    float4 hv = ((const float4*)g_h)[src * 32 + lane];
    float4 v = make_float4(w * hv.x, w * hv.y, w * hv.z, w * hv.w);
    float* p = out + dst * DIM + lane * 4;
    asm volatile("red.global.add.v4.f32 [%0], {%1,%2,%3,%4};"
                 :: "l"(p), "f"(v.x), "f"(v.y), "f"(v.z), "f"(v.w) : "memory");
}

// ---------------- kernel 5: finalize: /denom + bias, LayerNorm, GELU ----------------
__global__ __launch_bounds__(256) void k_finalize(
    float* __restrict__ out, const float* __restrict__ bias,
    const float* __restrict__ gamma, const float* __restrict__ beta)
{
    int n = (blockIdx.x * blockDim.x + threadIdx.x) >> 5;
    int lane = threadIdx.x & 31;
    if (n >= N_NODES) return;

    int head = lane >> 3;
    float inv = 1.f / (g_den[n * HEADS + head] + 1e-16f);
    float4 v = ((float4*)out)[n * 32 + lane];
    float4 b4 = ((const float4*)bias)[lane];
    v.x = v.x * inv + b4.x;
    v.y = v.y * inv + b4.y;
    v.z = v.z * inv + b4.z;
    v.w = v.w * inv + b4.w;

    float s  = v.x + v.y + v.z + v.w;
    float sq = v.x * v.x + v.y * v.y + v.z * v.z + v.w * v.w;
#pragma unroll
    for (int off = 16; off >= 1; off >>= 1) {
        s  += __shfl_xor_sync(0xffffffffu, s, off);
        sq += __shfl_xor_sync(0xffffffffu, sq, off);
    }
    float mu  = s * (1.f / 128.f);
    float var = sq * (1.f / 128.f) - mu * mu;
    float rstd = rsqrtf(var + 1e-5f);

    float4 g4 = ((const float4*)gamma)[lane];
    float4 e4 = ((const float4*)beta)[lane];
    float t;
    t = (v.x - mu) * rstd * g4.x + e4.x; v.x = 0.5f * t * (1.f + erff(t * 0.70710678118f));
    t = (v.y - mu) * rstd * g4.y + e4.y; v.y = 0.5f * t * (1.f + erff(t * 0.70710678118f));
    t = (v.z - mu) * rstd * g4.z + e4.z; v.z = 0.5f * t * (1.f + erff(t * 0.70710678118f));
    t = (v.w - mu) * rstd * g4.w + e4.w; v.w = 0.5f * t * (1.f + erff(t * 0.70710678118f));
    ((float4*)out)[n * 32 + lane] = v;
}

extern "C" void kernel_launch(void* const* d_in, const int* in_sizes, int n_in,
                              void* d_out, int out_size)
{
    const float* x     = (const float*)d_in[0];
    const void*  ei    = d_in[1];
    const float* W     = (const float*)d_in[2];
    const float* att_s = (const float*)d_in[3];
    const float* att_d = (const float*)d_in[4];
    const float* bias  = (const float*)d_in[5];
    const float* gamma = (const float*)d_in[6];
    const float* beta  = (const float*)d_in[7];
    float* out = (float*)d_out;

    // D: dtype detection (1 warp, negligible)
    k_detect<<<1, 32>>>((const unsigned*)ei);
    // 0: zero out + init max/den
    k_init<<<(N_NODES * 32 + 255) / 256, 256>>>((float4*)out);
    // 1: projection + attention dots (warp per node)
    k_gemm<<<(N_NODES * 32 + 255) / 256, 256>>>(x, W, att_s, att_d);
    // 2: segment max
    k_edge_max<<<(E2 + 255) / 256, 256>>>(ei);
    // 3: exp + denom
    k_edge_exp<<<(E2 + 255) / 256, 256>>>(ei);
    // 4: aggregate (warp per edge, 8 warps/block)
    k_edge_agg<<<(E2 + 7) / 8, 256>>>(ei, out);
    // 5: finalize (warp per node)
    k_finalize<<<(N_NODES * 32 + 255) / 256, 256>>>(out, bias, gamma, beta);
}

// round 3
// speedup vs baseline: 1.3907x; 1.3907x over previous
#include <cuda_runtime.h>
#include <cuda_bf16.h>
#include <math.h>

#define N_NODES 50000
#define N_EDGES 800000
#define HEADS   4
#define DIM     128
#define NPAD    50176            // 49 * 1024, padded node count for scan
#define SCAN_B  49

// -------- persistent scratch --------
__device__ float    g_h[N_NODES * DIM];       // 25.6 MB projected features
__device__ float    g_as[N_NODES * HEADS];
__device__ float    g_ad[N_NODES * HEADS];
__device__ int      g_cnt[NPAD];              // per-dst edge counts
__device__ int      g_offs[NPAD + 1];         // CSR row offsets (exclusive scan)
__device__ int      g_cursor[NPAD];           // scatter cursors
__device__ int      g_bsum[SCAN_B];           // per-block scan sums
__device__ int      g_src[N_EDGES];           // CSR: source node per slot
__device__ float    g_e4[N_EDGES * HEADS];    // CSR: leaky-relu'd logits per head
__device__ int      g_is64;

// fetch (src,dst) for raw edge e, int32 or int64 edge_index
__device__ __forceinline__ void load_edge(const void* __restrict__ ei, int e,
                                          int& src, int& dst) {
    if (g_is64) {
        const long long* p = (const long long*)ei;
        src = (int)p[e]; dst = (int)p[N_EDGES + e];
    } else {
        const int* p = (const int*)ei;
        src = p[e]; dst = p[N_EDGES + e];
    }
}

// ---------------- dtype detect: int64 => every odd 32-bit word is 0 ----------------
__global__ void k_detect(const unsigned* __restrict__ ei32) {
    if (threadIdx.x == 0) {
        int all_hi_zero = 1;
        for (int i = 0; i < 32; i++)
            if (ei32[2 * i + 1] != 0u) { all_hi_zero = 0; break; }
        g_is64 = all_hi_zero;
    }
}

// ---------------- zero counts ----------------
__global__ void k_zero() {
    int i = blockIdx.x * blockDim.x + threadIdx.x;
    if (i < NPAD) g_cnt[i] = 0;
}

// ---------------- histogram of dst ----------------
__global__ __launch_bounds__(256) void k_hist(const void* __restrict__ ei) {
    int e = blockIdx.x * blockDim.x + threadIdx.x;
    if (e >= N_EDGES) return;
    int dst;
    if (g_is64) dst = (int)((const long long*)ei)[N_EDGES + e];
    else        dst = ((const int*)ei)[N_EDGES + e];
    atomicAdd(&g_cnt[dst], 1);
}

// ---------------- two-level exclusive scan ----------------
__global__ __launch_bounds__(1024) void k_scan1() {
    __shared__ int s[1024];
    int t = threadIdx.x, b = blockIdx.x;
    int i = b * 1024 + t;
    int v = g_cnt[i];
    s[t] = v; __syncthreads();
#pragma unroll
    for (int off = 1; off < 1024; off <<= 1) {
        int x = (t >= off) ? s[t - off] : 0;
        __syncthreads();
        s[t] += x;
        __syncthreads();
    }
    g_offs[i] = s[t] - v;                       // exclusive
    if (t == 1023) g_bsum[b] = s[t];
}
__global__ void k_scan2() {
    if (threadIdx.x == 0) {
        int acc = 0;
        for (int b = 0; b < SCAN_B; b++) { int v = g_bsum[b]; g_bsum[b] = acc; acc += v; }
        g_offs[NPAD] = acc;                     // = N_EDGES
    }
}
__global__ __launch_bounds__(1024) void k_scan3() {
    int t = threadIdx.x, b = blockIdx.x;
    int i = b * 1024 + t;
    int o = g_offs[i] + g_bsum[b];
    g_offs[i] = o;
    g_cursor[i] = o;
}

// ---------------- gemm: h = x @ W ; attention dots fused ----------------
__global__ __launch_bounds__(256) void k_gemm(
    const float* __restrict__ x, const float* __restrict__ W,
    const float* __restrict__ att_s, const float* __restrict__ att_d)
{
    int warp = (blockIdx.x * blockDim.x + threadIdx.x) >> 5;
    int lane = threadIdx.x & 31;
    if (warp >= N_NODES) return;

    const float* xr = x + warp * DIM;
    float xv[4];
#pragma unroll
    for (int j = 0; j < 4; j++) xv[j] = xr[j * 32 + lane];

    float4 acc = make_float4(0.f, 0.f, 0.f, 0.f);
    const float4* W4 = (const float4*)W;
#pragma unroll 8
    for (int k = 0; k < 128; k++) {
        float xk = __shfl_sync(0xffffffffu, xv[k >> 5], k & 31);
        float4 w = W4[k * 32 + lane];
        acc.x = fmaf(xk, w.x, acc.x);
        acc.y = fmaf(xk, w.y, acc.y);
        acc.z = fmaf(xk, w.z, acc.z);
        acc.w = fmaf(xk, w.w, acc.w);
    }
    ((float4*)g_h)[warp * 32 + lane] = acc;

    int head = lane >> 3;
    int base = head * 32 + (lane & 7) * 4;
    float s = acc.x * att_s[base + 0] + acc.y * att_s[base + 1]
            + acc.z * att_s[base + 2] + acc.w * att_s[base + 3];
    float d = acc.x * att_d[base + 0] + acc.y * att_d[base + 1]
            + acc.z * att_d[base + 2] + acc.w * att_d[base + 3];
#pragma unroll
    for (int off = 4; off >= 1; off >>= 1) {
        s += __shfl_xor_sync(0xffffffffu, s, off);
        d += __shfl_xor_sync(0xffffffffu, d, off);
    }
    if ((lane & 7) == 0) {
        g_as[warp * HEADS + head] = s;
        g_ad[warp * HEADS + head] = d;
    }
}

// ---------------- scatter edges into CSR slots with precomputed logits ----------------
__global__ __launch_bounds__(256) void k_scatter(const void* __restrict__ ei) {
    int e = blockIdx.x * blockDim.x + threadIdx.x;
    if (e >= N_EDGES) return;
    int src, dst;
    load_edge(ei, e, src, dst);

    float4 a = *(const float4*)(g_as + src * HEADS);
    float4 b = *(const float4*)(g_ad + dst * HEADS);
    float4 ev = make_float4(a.x + b.x, a.y + b.y, a.z + b.z, a.w + b.w);
    ev.x = (ev.x < 0.f) ? 0.2f * ev.x : ev.x;
    ev.y = (ev.y < 0.f) ? 0.2f * ev.y : ev.y;
    ev.z = (ev.z < 0.f) ? 0.2f * ev.z : ev.z;
    ev.w = (ev.w < 0.f) ? 0.2f * ev.w : ev.w;

    int pos = atomicAdd(&g_cursor[dst], 1);
    g_src[pos] = src;
    *(float4*)(g_e4 + (size_t)pos * HEADS) = ev;
}

// ---------------- fused aggregate + softmax-normalize + bias + LN + GELU ----------------
// warp per destination node; accumulators in registers; no atomics.
__global__ __launch_bounds__(256) void k_agg(
    float* __restrict__ out, const float* __restrict__ bias,
    const float* __restrict__ gamma, const float* __restrict__ beta)
{
    int n = (blockIdx.x * blockDim.x + threadIdx.x) >> 5;
    int lane = threadIdx.x & 31;
    if (n >= N_NODES) return;
    int head = lane >> 3;

    int start = g_offs[n];
    int end   = g_offs[n + 1];

    float4 acc = make_float4(0.f, 0.f, 0.f, 0.f);
    float den = 0.f;

    // self loop: src = dst = n  (no max subtraction needed; e bounded ~8)
    {
        float e = g_as[n * HEADS + head] + g_ad[n * HEADS + head];
        e = (e < 0.f) ? 0.2f * e : e;
        float w = __expf(e);
        float4 hv = ((const float4*)g_h)[n * 32 + lane];
        acc.x = w * hv.x; acc.y = w * hv.y; acc.z = w * hv.z; acc.w = w * hv.w;
        den = w;
    }

    int src_next = (start < end) ? g_src[start] : 0;
    for (int j = start; j < end; j++) {
        int src = src_next;
        if (j + 1 < end) src_next = g_src[j + 1];
        float w = __expf(g_e4[(size_t)j * HEADS + head]);
        float4 hv = ((const float4*)g_h)[src * 32 + lane];
        acc.x = fmaf(w, hv.x, acc.x);
        acc.y = fmaf(w, hv.y, acc.y);
        acc.z = fmaf(w, hv.z, acc.z);
        acc.w = fmaf(w, hv.w, acc.w);
        den += w;
    }

    float inv = 1.f / (den + 1e-16f);
    float4 b4 = ((const float4*)bias)[lane];
    float4 v;
    v.x = acc.x * inv + b4.x;
    v.y = acc.y * inv + b4.y;
    v.z = acc.z * inv + b4.z;
    v.w = acc.w * inv + b4.w;

    float s  = v.x + v.y + v.z + v.w;
    float sq = v.x * v.x + v.y * v.y + v.z * v.z + v.w * v.w;
#pragma unroll
    for (int off = 16; off >= 1; off >>= 1) {
        s  += __shfl_xor_sync(0xffffffffu, s, off);
        sq += __shfl_xor_sync(0xffffffffu, sq, off);
    }
    float mu   = s * (1.f / 128.f);
    float var  = sq * (1.f / 128.f) - mu * mu;
    float rstd = rsqrtf(var + 1e-5f);

    float4 g4 = ((const float4*)gamma)[lane];
    float4 e4 = ((const float4*)beta)[lane];
    float t;
    t = (v.x - mu) * rstd * g4.x + e4.x; v.x = 0.5f * t * (1.f + erff(t * 0.70710678118f));
    t = (v.y - mu) * rstd * g4.y + e4.y; v.y = 0.5f * t * (1.f + erff(t * 0.70710678118f));
    t = (v.z - mu) * rstd * g4.z + e4.z; v.z = 0.5f * t * (1.f + erff(t * 0.70710678118f));
    t = (v.w - mu) * rstd * g4.w + e4.w; v.w = 0.5f * t * (1.f + erff(t * 0.70710678118f));
    ((float4*)out)[n * 32 + lane] = v;
}

extern "C" void kernel_launch(void* const* d_in, const int* in_sizes, int n_in,
                              void* d_out, int out_size)
{
    const float* x     = (const float*)d_in[0];
    const void*  ei    = d_in[1];
    const float* W     = (const float*)d_in[2];
    const float* att_s = (const float*)d_in[3];
    const float* att_d = (const float*)d_in[4];
    const float* bias  = (const float*)d_in[5];
    const float* gamma = (const float*)d_in[6];
    const float* beta  = (const float*)d_in[7];
    float* out = (float*)d_out;

    k_detect<<<1, 32>>>((const unsigned*)ei);
    k_zero<<<(NPAD + 255) / 256, 256>>>();
    k_hist<<<(N_EDGES + 255) / 256, 256>>>(ei);
    k_scan1<<<SCAN_B, 1024>>>();
    k_scan2<<<1, 32>>>();
    k_scan3<<<SCAN_B, 1024>>>();
    k_gemm<<<(N_NODES * 32 + 255) / 256, 256>>>(x, W, att_s, att_d);
    k_scatter<<<(N_EDGES + 255) / 256, 256>>>(ei);
    k_agg<<<(N_NODES * 32 + 255) / 256, 256>>>(out, bias, gamma, beta);
}

// round 4
// speedup vs baseline: 1.5315x; 1.1013x over previous
#include <cuda_runtime.h>
#include <cuda_bf16.h>
#include <math.h>

#define N_NODES 50000
#define N_EDGES 800000
#define HEADS   4
#define DIM     128
#define NPAD    50176            // 49 * 1024
#define SCAN_B  49

// -------- persistent scratch --------
__device__ float    g_h[N_NODES * DIM];       // 25.6 MB projected features
__device__ float    g_as[N_NODES * HEADS];
__device__ float    g_ad[N_NODES * HEADS];
__device__ int      g_cnt[NPAD];
__device__ int      g_offs[NPAD];             // CSR row offsets
__device__ int      g_cursor[NPAD];
__device__ int      g_bsum[SCAN_B];
__device__ int      g_src[N_EDGES];           // CSR: source node per slot
__device__ int      g_is64;

// ---------------- dtype detect ----------------
__global__ void k_detect(const unsigned* __restrict__ ei32) {
    if (threadIdx.x == 0) {
        int all_hi_zero = 1;
        for (int i = 0; i < 32; i++)
            if (ei32[2 * i + 1] != 0u) { all_hi_zero = 0; break; }
        g_is64 = all_hi_zero;
    }
}

// ---------------- zero counts ----------------
__global__ void k_zero() {
    int i = blockIdx.x * blockDim.x + threadIdx.x;
    if (i < NPAD) g_cnt[i] = 0;
}

// ---------------- histogram of dst ----------------
__global__ __launch_bounds__(256) void k_hist(const void* __restrict__ ei) {
    int e = blockIdx.x * blockDim.x + threadIdx.x;
    if (e >= N_EDGES) return;
    int dst;
    if (g_is64) dst = (int)((const long long*)ei)[N_EDGES + e];
    else        dst = ((const int*)ei)[N_EDGES + e];
    atomicAdd(&g_cnt[dst], 1);
}

// ---------------- scan stage 1: per-block exclusive scan + block sums ----------------
__global__ __launch_bounds__(1024) void k_scan1() {
    __shared__ int s[1024];
    int t = threadIdx.x, b = blockIdx.x;
    int i = b * 1024 + t;
    int v = g_cnt[i];
    s[t] = v; __syncthreads();
#pragma unroll
    for (int off = 1; off < 1024; off <<= 1) {
        int x = (t >= off) ? s[t - off] : 0;
        __syncthreads();
        s[t] += x;
        __syncthreads();
    }
    g_offs[i] = s[t] - v;                       // exclusive within block
    if (t == 1023) g_bsum[b] = s[t];
}

// ---------------- scan stage 2: add block prefix (each block reduces bsum itself) ----------------
__global__ __launch_bounds__(1024) void k_scan3() {
    __shared__ int sp[64];
    __shared__ int pref;
    int t = threadIdx.x, b = blockIdx.x;
    if (t < 64) sp[t] = (t < SCAN_B && t < b) ? g_bsum[t] : 0;
    __syncthreads();
    if (t == 0) {
        int acc = 0;
#pragma unroll
        for (int k = 0; k < 64; k++) acc += sp[k];
        pref = acc;
    }
    __syncthreads();
    int i = b * 1024 + t;
    int o = g_offs[i] + pref;
    g_offs[i] = o;
    g_cursor[i] = o;
}

// ---------------- gemm: h = x @ W ; attention dots fused ----------------
__global__ __launch_bounds__(256) void k_gemm(
    const float* __restrict__ x, const float* __restrict__ W,
    const float* __restrict__ att_s, const float* __restrict__ att_d)
{
    int warp = (blockIdx.x * blockDim.x + threadIdx.x) >> 5;
    int lane = threadIdx.x & 31;
    if (warp >= N_NODES) return;

    const float* xr = x + warp * DIM;
    float xv[4];
#pragma unroll
    for (int j = 0; j < 4; j++) xv[j] = xr[j * 32 + lane];

    float4 acc = make_float4(0.f, 0.f, 0.f, 0.f);
    const float4* W4 = (const float4*)W;
#pragma unroll 8
    for (int k = 0; k < 128; k++) {
        float xk = __shfl_sync(0xffffffffu, xv[k >> 5], k & 31);
        float4 w = W4[k * 32 + lane];
        acc.x = fmaf(xk, w.x, acc.x);
        acc.y = fmaf(xk, w.y, acc.y);
        acc.z = fmaf(xk, w.z, acc.z);
        acc.w = fmaf(xk, w.w, acc.w);
    }
    ((float4*)g_h)[warp * 32 + lane] = acc;

    int head = lane >> 3;
    int base = head * 32 + (lane & 7) * 4;
    float s = acc.x * att_s[base + 0] + acc.y * att_s[base + 1]
            + acc.z * att_s[base + 2] + acc.w * att_s[base + 3];
    float d = acc.x * att_d[base + 0] + acc.y * att_d[base + 1]
            + acc.z * att_d[base + 2] + acc.w * att_d[base + 3];
#pragma unroll
    for (int off = 4; off >= 1; off >>= 1) {
        s += __shfl_xor_sync(0xffffffffu, s, off);
        d += __shfl_xor_sync(0xffffffffu, d, off);
    }
    if ((lane & 7) == 0) {
        g_as[warp * HEADS + head] = s;
        g_ad[warp * HEADS + head] = d;
    }
}

// ---------------- scatter: CSR src only ----------------
__global__ __launch_bounds__(256) void k_scatter(const void* __restrict__ ei) {
    int e = blockIdx.x * blockDim.x + threadIdx.x;
    if (e >= N_EDGES) return;
    int src, dst;
    if (g_is64) {
        const long long* p = (const long long*)ei;
        src = (int)p[e]; dst = (int)p[N_EDGES + e];
    } else {
        const int* p = (const int*)ei;
        src = p[e]; dst = p[N_EDGES + e];
    }
    int pos = atomicAdd(&g_cursor[dst], 1);
    g_src[pos] = src;
}

// ---------------- fused aggregate + softmax + bias + LN + GELU ----------------
__global__ __launch_bounds__(256) void k_agg(
    float* __restrict__ out, const float* __restrict__ bias,
    const float* __restrict__ gamma, const float* __restrict__ beta)
{
    int n = (blockIdx.x * blockDim.x + threadIdx.x) >> 5;
    int lane = threadIdx.x & 31;
    if (n >= N_NODES) return;
    int head = lane >> 3;

    float ad = g_ad[n * HEADS + head];          // loop-invariant dst term

    int start = g_offs[n];
    int end   = g_offs[n + 1];

    // self loop
    float4 acc0, acc1 = make_float4(0.f, 0.f, 0.f, 0.f);
    float den0, den1 = 0.f;
    {
        float e = g_as[n * HEADS + head] + ad;
        e = (e < 0.f) ? 0.2f * e : e;
        float w = __expf(e);                     // |e| bounded (~8): no max-shift needed
        float4 hv = ((const float4*)g_h)[n * 32 + lane];
        acc0 = make_float4(w * hv.x, w * hv.y, w * hv.z, w * hv.w);
        den0 = w;
    }

    const float4* H4 = (const float4*)g_h;
    int j = start;
    for (; j + 1 < end; j += 2) {
        int s0 = g_src[j];
        int s1 = g_src[j + 1];
        float as0 = g_as[s0 * HEADS + head];
        float as1 = g_as[s1 * HEADS + head];
        float4 h0 = H4[s0 * 32 + lane];
        float4 h1 = H4[s1 * 32 + lane];
        float e0 = as0 + ad; e0 = (e0 < 0.f) ? 0.2f * e0 : e0;
        float e1 = as1 + ad; e1 = (e1 < 0.f) ? 0.2f * e1 : e1;
        float w0 = __expf(e0);
        float w1 = __expf(e1);
        acc0.x = fmaf(w0, h0.x, acc0.x); acc1.x = fmaf(w1, h1.x, acc1.x);
        acc0.y = fmaf(w0, h0.y, acc0.y); acc1.y = fmaf(w1, h1.y, acc1.y);
        acc0.z = fmaf(w0, h0.z, acc0.z); acc1.z = fmaf(w1, h1.z, acc1.z);
        acc0.w = fmaf(w0, h0.w, acc0.w); acc1.w = fmaf(w1, h1.w, acc1.w);
        den0 += w0; den1 += w1;
    }
    if (j < end) {
        int s0 = g_src[j];
        float as0 = g_as[s0 * HEADS + head];
        float4 h0 = H4[s0 * 32 + lane];
        float e0 = as0 + ad; e0 = (e0 < 0.f) ? 0.2f * e0 : e0;
        float w0 = __expf(e0);
        acc0.x = fmaf(w0, h0.x, acc0.x);
        acc0.y = fmaf(w0, h0.y, acc0.y);
        acc0.z = fmaf(w0, h0.z, acc0.z);
        acc0.w = fmaf(w0, h0.w, acc0.w);
        den0 += w0;
    }
    float den = den0 + den1;
    float4 acc = make_float4(acc0.x + acc1.x, acc0.y + acc1.y,
                             acc0.z + acc1.z, acc0.w + acc1.w);

    float inv = 1.f / (den + 1e-16f);
    float4 b4 = ((const float4*)bias)[lane];
    float4 v;
    v.x = acc.x * inv + b4.x;
    v.y = acc.y * inv + b4.y;
    v.z = acc.z * inv + b4.z;
    v.w = acc.w * inv + b4.w;

    float s  = v.x + v.y + v.z + v.w;
    float sq = v.x * v.x + v.y * v.y + v.z * v.z + v.w * v.w;
#pragma unroll
    for (int off = 16; off >= 1; off >>= 1) {
        s  += __shfl_xor_sync(0xffffffffu, s, off);
        sq += __shfl_xor_sync(0xffffffffu, sq, off);
    }
    float mu   = s * (1.f / 128.f);
    float var  = sq * (1.f / 128.f) - mu * mu;
    float rstd = rsqrtf(var + 1e-5f);

    float4 g4 = ((const float4*)gamma)[lane];
    float4 e4 = ((const float4*)beta)[lane];
    float t;
    t = (v.x - mu) * rstd * g4.x + e4.x; v.x = 0.5f * t * (1.f + erff(t * 0.70710678118f));
    t = (v.y - mu) * rstd * g4.y + e4.y; v.y = 0.5f * t * (1.f + erff(t * 0.70710678118f));
    t = (v.z - mu) * rstd * g4.z + e4.z; v.z = 0.5f * t * (1.f + erff(t * 0.70710678118f));
    t = (v.w - mu) * rstd * g4.w + e4.w; v.w = 0.5f * t * (1.f + erff(t * 0.70710678118f));
    ((float4*)out)[n * 32 + lane] = v;
}

extern "C" void kernel_launch(void* const* d_in, const int* in_sizes, int n_in,
                              void* d_out, int out_size)
{
    const float* x     = (const float*)d_in[0];
    const void*  ei    = d_in[1];
    const float* W     = (const float*)d_in[2];
    const float* att_s = (const float*)d_in[3];
    const float* att_d = (const float*)d_in[4];
    const float* bias  = (const float*)d_in[5];
    const float* gamma = (const float*)d_in[6];
    const float* beta  = (const float*)d_in[7];
    float* out = (float*)d_out;

    // one-time resources for the fork-join capture pattern (not device memory)
    static cudaStream_t sB = nullptr;
    static cudaEvent_t evFork = nullptr, evJoin = nullptr;
    if (sB == nullptr) {
        cudaStreamCreateWithFlags(&sB, cudaStreamNonBlocking);
        cudaEventCreateWithFlags(&evFork, cudaEventDisableTiming);
        cudaEventCreateWithFlags(&evJoin, cudaEventDisableTiming);
    }

    // fork: stream B builds the CSR index while the capture stream runs the GEMM
    cudaEventRecord(evFork, 0);
    cudaStreamWaitEvent(sB, evFork, 0);

    k_detect<<<1, 32, 0, sB>>>((const unsigned*)ei);
    k_zero<<<(NPAD + 255) / 256, 256, 0, sB>>>();
    k_hist<<<(N_EDGES + 255) / 256, 256, 0, sB>>>(ei);
    k_scan1<<<SCAN_B, 1024, 0, sB>>>();
    k_scan3<<<SCAN_B, 1024, 0, sB>>>();
    k_scatter<<<(N_EDGES + 255) / 256, 256, 0, sB>>>(ei);

    k_gemm<<<(N_NODES * 32 + 255) / 256, 256>>>(x, W, att_s, att_d);

    // join
    cudaEventRecord(evJoin, sB);
    cudaStreamWaitEvent(0, evJoin, 0);

    k_agg<<<(N_NODES * 32 + 255) / 256, 256>>>(out, bias, gamma, beta);
}

// round 5
// speedup vs baseline: 1.5515x; 1.0130x over previous
#include <cuda_runtime.h>
#include <cuda_fp16.h>
#include <math.h>

#define N_NODES 50000
#define N_EDGES 800000
#define HEADS   4
#define DIM     128
#define NPAD    50176            // 49 * 1024
#define SCAN_B  49

// -------- persistent scratch --------
__device__ __half   g_h16[N_NODES * DIM];     // 12.8 MB projected features (fp16)
__device__ float    g_as[N_NODES * HEADS];
__device__ float    g_ad[N_NODES * HEADS];
__device__ int      g_cnt[NPAD];
__device__ int      g_offs[NPAD];
__device__ int      g_cursor[NPAD];
__device__ int      g_bsum[SCAN_B];
__device__ int      g_arrive;
__device__ int      g_src[N_EDGES];
__device__ int      g_is64;

// ---------------- prep: zero counters + reset scan counter + dtype detect ----------------
__global__ void k_prep(const unsigned* __restrict__ ei32) {
    int i = blockIdx.x * blockDim.x + threadIdx.x;
    if (i < NPAD) g_cnt[i] = 0;
    if (i == 0) {
        g_arrive = 0;
        int all_hi_zero = 1;
        for (int k = 0; k < 32; k++)
            if (ei32[2 * k + 1] != 0u) { all_hi_zero = 0; break; }
        g_is64 = all_hi_zero;
    }
}

// ---------------- histogram of dst (4 edges / thread) ----------------
__global__ __launch_bounds__(256) void k_hist(const void* __restrict__ ei) {
    int i = blockIdx.x * blockDim.x + threadIdx.x;
    if (i >= N_EDGES / 4) return;
    if (g_is64) {
        const longlong2* p = (const longlong2*)((const long long*)ei + N_EDGES);
        longlong2 a = p[2 * i], b = p[2 * i + 1];
        atomicAdd(&g_cnt[(int)a.x], 1);
        atomicAdd(&g_cnt[(int)a.y], 1);
        atomicAdd(&g_cnt[(int)b.x], 1);
        atomicAdd(&g_cnt[(int)b.y], 1);
    } else {
        const int4* p = (const int4*)((const int*)ei + N_EDGES);
        int4 d = p[i];
        atomicAdd(&g_cnt[d.x], 1);
        atomicAdd(&g_cnt[d.y], 1);
        atomicAdd(&g_cnt[d.z], 1);
        atomicAdd(&g_cnt[d.w], 1);
    }
}

// ---------------- single-kernel exclusive scan (49 co-resident blocks) ----------------
__global__ __launch_bounds__(1024) void k_scan() {
    __shared__ int s[1024];
    __shared__ int pref;
    int t = threadIdx.x, b = blockIdx.x;
    int i = b * 1024 + t;
    int v = g_cnt[i];
    s[t] = v; __syncthreads();
#pragma unroll
    for (int off = 1; off < 1024; off <<= 1) {
        int x = (t >= off) ? s[t - off] : 0;
        __syncthreads();
        s[t] += x;
        __syncthreads();
    }
    int excl = s[t] - v;
    if (t == 1023) {
        g_bsum[b] = s[t];
        __threadfence();
        atomicAdd(&g_arrive, 1);
    }
    if (t == 0) {
        while (atomicAdd(&g_arrive, 0) < SCAN_B) { }
        int a = 0;
        for (int k = 0; k < b; k++) a += g_bsum[k];
        pref = a;
    }
    __syncthreads();
    int o = excl + pref;
    g_offs[i] = o;
    g_cursor[i] = o;
}

// ---------------- scatter: CSR src only ----------------
__global__ __launch_bounds__(256) void k_scatter(const void* __restrict__ ei) {
    int e = blockIdx.x * blockDim.x + threadIdx.x;
    if (e >= N_EDGES) return;
    int src, dst;
    if (g_is64) {
        const long long* p = (const long long*)ei;
        src = (int)p[e]; dst = (int)p[N_EDGES + e];
    } else {
        const int* p = (const int*)ei;
        src = p[e]; dst = p[N_EDGES + e];
    }
    int pos = atomicAdd(&g_cursor[dst], 1);
    g_src[pos] = src;
}

// ---------------- gemm: h = x @ W (fp16 out) ; attention dots fused ----------------
__global__ __launch_bounds__(256) void k_gemm(
    const float* __restrict__ x, const float* __restrict__ W,
    const float* __restrict__ att_s, const float* __restrict__ att_d)
{
    int warp = (blockIdx.x * blockDim.x + threadIdx.x) >> 5;
    int lane = threadIdx.x & 31;
    if (warp >= N_NODES) return;

    const float* xr = x + warp * DIM;
    float xv[4];
#pragma unroll
    for (int j = 0; j < 4; j++) xv[j] = xr[j * 32 + lane];

    float4 acc = make_float4(0.f, 0.f, 0.f, 0.f);
    const float4* W4 = (const float4*)W;
#pragma unroll 8
    for (int k = 0; k < 128; k++) {
        float xk = __shfl_sync(0xffffffffu, xv[k >> 5], k & 31);
        float4 w = W4[k * 32 + lane];
        acc.x = fmaf(xk, w.x, acc.x);
        acc.y = fmaf(xk, w.y, acc.y);
        acc.z = fmaf(xk, w.z, acc.z);
        acc.w = fmaf(xk, w.w, acc.w);
    }
    // store 4 consecutive halves (cols lane*4..+3)
    __half2 h0 = __floats2half2_rn(acc.x, acc.y);
    __half2 h1 = __floats2half2_rn(acc.z, acc.w);
    ((__half2*)g_h16)[warp * 64 + lane * 2]     = h0;
    ((__half2*)g_h16)[warp * 64 + lane * 2 + 1] = h1;

    int head = lane >> 3;
    int base = head * 32 + (lane & 7) * 4;
    float s = acc.x * att_s[base + 0] + acc.y * att_s[base + 1]
            + acc.z * att_s[base + 2] + acc.w * att_s[base + 3];
    float d = acc.x * att_d[base + 0] + acc.y * att_d[base + 1]
            + acc.z * att_d[base + 2] + acc.w * att_d[base + 3];
#pragma unroll
    for (int off = 4; off >= 1; off >>= 1) {
        s += __shfl_xor_sync(0xffffffffu, s, off);
        d += __shfl_xor_sync(0xffffffffu, d, off);
    }
    if ((lane & 7) == 0) {
        g_as[warp * HEADS + head] = s;
        g_ad[warp * HEADS + head] = d;
    }
}

// lrelu + exp helper
__device__ __forceinline__ float wgt(float as, float ad) {
    float e = as + ad;
    e = (e < 0.f) ? 0.2f * e : e;
    return __expf(e);
}
// fma 4 halves into a float4 accumulator
__device__ __forceinline__ void acc4(float4& a, float w, uint2 r) {
    __half2* ph = (__half2*)&r;
    float2 lo = __half22float2(ph[0]);
    float2 hi = __half22float2(ph[1]);
    a.x = fmaf(w, lo.x, a.x);
    a.y = fmaf(w, lo.y, a.y);
    a.z = fmaf(w, hi.x, a.z);
    a.w = fmaf(w, hi.y, a.w);
}

// ---------------- fused aggregate + softmax + bias + LN + GELU ----------------
__global__ __launch_bounds__(256) void k_agg(
    float* __restrict__ out, const float* __restrict__ bias,
    const float* __restrict__ gamma, const float* __restrict__ beta)
{
    int n = (blockIdx.x * blockDim.x + threadIdx.x) >> 5;
    int lane = threadIdx.x & 31;
    if (n >= N_NODES) return;
    int head = lane >> 3;

    const uint2* H = (const uint2*)g_h16;     // 32 uint2 (= 4 halves each) per row
    float ad = g_ad[n * HEADS + head];

    int start = g_offs[n];
    int end   = g_offs[n + 1];

    float4 a0 = make_float4(0.f, 0.f, 0.f, 0.f), a1 = a0, a2 = a0, a3 = a0;
    float d0 = 0.f, d1 = 0.f, d2 = 0.f, d3 = 0.f;

    // self loop
    {
        float w = wgt(g_as[n * HEADS + head], ad);
        acc4(a0, w, H[n * 32 + lane]);
        d0 = w;
    }

    int j = start;
    for (; j + 3 < end; j += 4) {
        int s0 = g_src[j], s1 = g_src[j + 1], s2 = g_src[j + 2], s3 = g_src[j + 3];
        float w0 = wgt(g_as[s0 * HEADS + head], ad);
        float w1 = wgt(g_as[s1 * HEADS + head], ad);
        float w2 = wgt(g_as[s2 * HEADS + head], ad);
        float w3 = wgt(g_as[s3 * HEADS + head], ad);
        uint2 r0 = H[s0 * 32 + lane];
        uint2 r1 = H[s1 * 32 + lane];
        uint2 r2 = H[s2 * 32 + lane];
        uint2 r3 = H[s3 * 32 + lane];
        acc4(a0, w0, r0); d0 += w0;
        acc4(a1, w1, r1); d1 += w1;
        acc4(a2, w2, r2); d2 += w2;
        acc4(a3, w3, r3); d3 += w3;
    }
    for (; j < end; j++) {
        int s0 = g_src[j];
        float w0 = wgt(g_as[s0 * HEADS + head], ad);
        acc4(a0, w0, H[s0 * 32 + lane]);
        d0 += w0;
    }

    float den = (d0 + d1) + (d2 + d3);
    float4 acc = make_float4((a0.x + a1.x) + (a2.x + a3.x),
                             (a0.y + a1.y) + (a2.y + a3.y),
                             (a0.z + a1.z) + (a2.z + a3.z),
                             (a0.w + a1.w) + (a2.w + a3.w));

    float inv = 1.f / (den + 1e-16f);
    float4 b4 = ((const float4*)bias)[lane];
    float4 v;
    v.x = acc.x * inv + b4.x;
    v.y = acc.y * inv + b4.y;
    v.z = acc.z * inv + b4.z;
    v.w = acc.w * inv + b4.w;

    float s  = v.x + v.y + v.z + v.w;
    float sq = v.x * v.x + v.y * v.y + v.z * v.z + v.w * v.w;
#pragma unroll
    for (int off = 16; off >= 1; off >>= 1) {
        s  += __shfl_xor_sync(0xffffffffu, s, off);
        sq += __shfl_xor_sync(0xffffffffu, sq, off);
    }
    float mu   = s * (1.f / 128.f);
    float var  = sq * (1.f / 128.f) - mu * mu;
    float rstd = rsqrtf(var + 1e-5f);

    float4 g4 = ((const float4*)gamma)[lane];
    float4 e4 = ((const float4*)beta)[lane];
    float t;
    t = (v.x - mu) * rstd * g4.x + e4.x; v.x = 0.5f * t * (1.f + erff(t * 0.70710678118f));
    t = (v.y - mu) * rstd * g4.y + e4.y; v.y = 0.5f * t * (1.f + erff(t * 0.70710678118f));
    t = (v.z - mu) * rstd * g4.z + e4.z; v.z = 0.5f * t * (1.f + erff(t * 0.70710678118f));
    t = (v.w - mu) * rstd * g4.w + e4.w; v.w = 0.5f * t * (1.f + erff(t * 0.70710678118f));
    ((float4*)out)[n * 32 + lane] = v;
}

extern "C" void kernel_launch(void* const* d_in, const int* in_sizes, int n_in,
                              void* d_out, int out_size)
{
    const float* x     = (const float*)d_in[0];
    const void*  ei    = d_in[1];
    const float* W     = (const float*)d_in[2];
    const float* att_s = (const float*)d_in[3];
    const float* att_d = (const float*)d_in[4];
    const float* bias  = (const float*)d_in[5];
    const float* gamma = (const float*)d_in[6];
    const float* beta  = (const float*)d_in[7];
    float* out = (float*)d_out;

    static cudaStream_t sB = nullptr;
    static cudaEvent_t evFork = nullptr, evJoin = nullptr;
    if (sB == nullptr) {
        cudaStreamCreateWithFlags(&sB, cudaStreamNonBlocking);
        cudaEventCreateWithFlags(&evFork, cudaEventDisableTiming);
        cudaEventCreateWithFlags(&evJoin, cudaEventDisableTiming);
    }

    // fork: stream B builds CSR while capture stream runs the GEMM
    cudaEventRecord(evFork, 0);
    cudaStreamWaitEvent(sB, evFork, 0);

    k_prep<<<(NPAD + 255) / 256, 256, 0, sB>>>((const unsigned*)ei);
    k_hist<<<(N_EDGES / 4 + 255) / 256, 256, 0, sB>>>(ei);
    k_scan<<<SCAN_B, 1024, 0, sB>>>();
    k_scatter<<<(N_EDGES + 255) / 256, 256, 0, sB>>>(ei);

    k_gemm<<<(N_NODES * 32 + 255) / 256, 256>>>(x, W, att_s, att_d);

    cudaEventRecord(evJoin, sB);
    cudaStreamWaitEvent(0, evJoin, 0);

    k_agg<<<(N_NODES * 32 + 255) / 256, 256>>>(out, bias, gamma, beta);
}

// round 7
// speedup vs baseline: 2.0713x; 1.3351x over previous
#include <cuda_runtime.h>
#include <cuda_fp16.h>
#include <math.h>

#define N_NODES 50000
#define N_EDGES 800000
#define HEADS   4
#define DIM     128
#define NPAD    50176            // 49 * 1024
#define SCAN_B  49

// -------- persistent scratch --------
__device__ __half   g_h16[N_NODES * DIM];     // 12.8 MB projected features (fp16)
__device__ float    g_as[N_NODES * HEADS];
__device__ float    g_ad[N_NODES * HEADS];
__device__ int      g_cnt[NPAD];
__device__ int      g_offs[NPAD];
__device__ int      g_cursor[NPAD];
__device__ int      g_bsum[SCAN_B];
__device__ int      g_arrive;
__device__ int      g_src[N_EDGES];
__device__ int      g_is64;

// ---------------- prep: zero counters + reset scan counter + dtype detect ----------------
__global__ void k_prep(const unsigned* __restrict__ ei32) {
    int i = blockIdx.x * blockDim.x + threadIdx.x;
    if (i < NPAD) g_cnt[i] = 0;
    if (i == 0) {
        g_arrive = 0;
        int all_hi_zero = 1;
        for (int k = 0; k < 32; k++)
            if (ei32[2 * k + 1] != 0u) { all_hi_zero = 0; break; }
        g_is64 = all_hi_zero;
    }
}

// ---------------- histogram of dst (4 edges / thread) ----------------
__global__ __launch_bounds__(256) void k_hist(const void* __restrict__ ei) {
    int i = blockIdx.x * blockDim.x + threadIdx.x;
    if (i >= N_EDGES / 4) return;
    if (g_is64) {
        const longlong2* p = (const longlong2*)((const long long*)ei + N_EDGES);
        longlong2 a = p[2 * i], b = p[2 * i + 1];
        atomicAdd(&g_cnt[(int)a.x], 1);
        atomicAdd(&g_cnt[(int)a.y], 1);
        atomicAdd(&g_cnt[(int)b.x], 1);
        atomicAdd(&g_cnt[(int)b.y], 1);
    } else {
        const int4* p = (const int4*)((const int*)ei + N_EDGES);
        int4 d = p[i];
        atomicAdd(&g_cnt[d.x], 1);
        atomicAdd(&g_cnt[d.y], 1);
        atomicAdd(&g_cnt[d.z], 1);
        atomicAdd(&g_cnt[d.w], 1);
    }
}

// ---------------- single-kernel exclusive scan (49 co-resident blocks) ----------------
__global__ __launch_bounds__(1024) void k_scan() {
    __shared__ int s[1024];
    __shared__ int pref;
    int t = threadIdx.x, b = blockIdx.x;
    int i = b * 1024 + t;
    int v = g_cnt[i];
    s[t] = v; __syncthreads();
#pragma unroll
    for (int off = 1; off < 1024; off <<= 1) {
        int x = (t >= off) ? s[t - off] : 0;
        __syncthreads();
        s[t] += x;
        __syncthreads();
    }
    int excl = s[t] - v;
    if (t == 1023) {
        g_bsum[b] = s[t];
        __threadfence();
        atomicAdd(&g_arrive, 1);
    }
    if (t == 0) {
        while (atomicAdd(&g_arrive, 0) < SCAN_B) { }
        int a = 0;
        for (int k = 0; k < b; k++) a += g_bsum[k];
        pref = a;
    }
    __syncthreads();
    int o = excl + pref;
    g_offs[i] = o;
    g_cursor[i] = o;
}

// ---------------- scatter: 4 edges / thread, CSR src only ----------------
__global__ __launch_bounds__(256) void k_scatter(const void* __restrict__ ei) {
    int i = blockIdx.x * blockDim.x + threadIdx.x;
    if (i >= N_EDGES / 4) return;
    int s[4], d[4];
    if (g_is64) {
        const longlong2* ps = (const longlong2*)ei;
        const longlong2* pd = (const longlong2*)((const long long*)ei + N_EDGES);
        longlong2 s01 = ps[2 * i], s23 = ps[2 * i + 1];
        longlong2 d01 = pd[2 * i], d23 = pd[2 * i + 1];
        s[0] = (int)s01.x; s[1] = (int)s01.y; s[2] = (int)s23.x; s[3] = (int)s23.y;
        d[0] = (int)d01.x; d[1] = (int)d01.y; d[2] = (int)d23.x; d[3] = (int)d23.y;
    } else {
        int4 s4 = ((const int4*)ei)[i];
        int4 d4 = ((const int4*)((const int*)ei + N_EDGES))[i];
        s[0] = s4.x; s[1] = s4.y; s[2] = s4.z; s[3] = s4.w;
        d[0] = d4.x; d[1] = d4.y; d[2] = d4.z; d[3] = d4.w;
    }
    int p0 = atomicAdd(&g_cursor[d[0]], 1);
    int p1 = atomicAdd(&g_cursor[d[1]], 1);
    int p2 = atomicAdd(&g_cursor[d[2]], 1);
    int p3 = atomicAdd(&g_cursor[d[3]], 1);
    g_src[p0] = s[0];
    g_src[p1] = s[1];
    g_src[p2] = s[2];
    g_src[p3] = s[3];
}

// ---------------- gemm: 4 nodes per warp (16 FMA per W load) ----------------
__global__ __launch_bounds__(256) void k_gemm(
    const float* __restrict__ x, const float* __restrict__ W,
    const float* __restrict__ att_s, const float* __restrict__ att_d)
{
    int warp = (blockIdx.x * blockDim.x + threadIdx.x) >> 5;
    int lane = threadIdx.x & 31;
    int n0 = warp * 4;
    if (n0 >= N_NODES) return;     // N_NODES % 4 == 0, always 4 valid nodes

    float xv[4][4];
#pragma unroll
    for (int i = 0; i < 4; i++) {
        const float* xr = x + (n0 + i) * DIM;
#pragma unroll
        for (int j = 0; j < 4; j++) xv[i][j] = xr[j * 32 + lane];
    }

    float4 acc[4];
#pragma unroll
    for (int i = 0; i < 4; i++) acc[i] = make_float4(0.f, 0.f, 0.f, 0.f);

    const float4* W4 = (const float4*)W;
#pragma unroll 4
    for (int k = 0; k < 128; k++) {
        float4 w = W4[k * 32 + lane];
#pragma unroll
        for (int i = 0; i < 4; i++) {
            float xk = __shfl_sync(0xffffffffu, xv[i][k >> 5], k & 31);
            acc[i].x = fmaf(xk, w.x, acc[i].x);
            acc[i].y = fmaf(xk, w.y, acc[i].y);
            acc[i].z = fmaf(xk, w.z, acc[i].z);
            acc[i].w = fmaf(xk, w.w, acc[i].w);
        }
    }

    int head = lane >> 3;
    int base = head * 32 + (lane & 7) * 4;
    float as0 = att_s[base + 0], as1 = att_s[base + 1],
          as2 = att_s[base + 2], as3 = att_s[base + 3];
    float ad0 = att_d[base + 0], ad1 = att_d[base + 1],
          ad2 = att_d[base + 2], ad3 = att_d[base + 3];

#pragma unroll
    for (int i = 0; i < 4; i++) {
        int n = n0 + i;
        __half2 h0 = __floats2half2_rn(acc[i].x, acc[i].y);
        __half2 h1 = __floats2half2_rn(acc[i].z, acc[i].w);
        uint2 pk;
        pk.x = *(unsigned*)&h0;
        pk.y = *(unsigned*)&h1;
        ((uint2*)g_h16)[n * 32 + lane] = pk;

        float s = acc[i].x * as0 + acc[i].y * as1 + acc[i].z * as2 + acc[i].w * as3;
        float d = acc[i].x * ad0 + acc[i].y * ad1 + acc[i].z * ad2 + acc[i].w * ad3;
#pragma unroll
        for (int off = 4; off >= 1; off >>= 1) {
            s += __shfl_xor_sync(0xffffffffu, s, off);
            d += __shfl_xor_sync(0xffffffffu, d, off);
        }
        if ((lane & 7) == 0) {
            g_as[n * HEADS + head] = s;
            g_ad[n * HEADS + head] = d;
        }
    }
}

// lrelu + exp
__device__ __forceinline__ float wgt(float as, float ad) {
    float e = as + ad;
    e = (e < 0.f) ? 0.2f * e : e;
    return __expf(e);
}
__device__ __forceinline__ void acc4(float4& a, float w, uint2 r) {
    __half2* ph = (__half2*)&r;
    float2 lo = __half22float2(ph[0]);
    float2 hi = __half22float2(ph[1]);
    a.x = fmaf(w, lo.x, a.x);
    a.y = fmaf(w, lo.y, a.y);
    a.z = fmaf(w, hi.x, a.z);
    a.w = fmaf(w, hi.y, a.w);
}

// ---------------- fused aggregate + softmax + bias + LN + GELU ----------------
__global__ __launch_bounds__(256) void k_agg(
    float* __restrict__ out, const float* __restrict__ bias,
    const float* __restrict__ gamma, const float* __restrict__ beta)
{
    int n = (blockIdx.x * blockDim.x + threadIdx.x) >> 5;
    int lane = threadIdx.x & 31;
    if (n >= N_NODES) return;
    int head = lane >> 3;

    const uint2* H = (const uint2*)g_h16;
    float ad = __ldg(&g_ad[n * HEADS + head]);

    int start = g_offs[n];
    int end   = g_offs[n + 1];

    float4 a0 = make_float4(0.f, 0.f, 0.f, 0.f), a1 = a0, a2 = a0, a3 = a0;
    float d0 = 0.f, d1 = 0.f, d2 = 0.f, d3 = 0.f;

    // self loop
    {
        float w = wgt(__ldg(&g_as[n * HEADS + head]), ad);
        acc4(a0, w, __ldg(&H[n * 32 + lane]));
        d0 = w;
    }

    int j = start;
    // unroll 8: 16 independent gathers in flight
    for (; j + 7 < end; j += 8) {
        int s[8];
#pragma unroll
        for (int q = 0; q < 8; q++) s[q] = __ldg(&g_src[j + q]);
        float as[8];
#pragma unroll
        for (int q = 0; q < 8; q++) as[q] = __ldg(&g_as[s[q] * HEADS + head]);
        uint2 r[8];
#pragma unroll
        for (int q = 0; q < 8; q++) r[q] = __ldg(&H[s[q] * 32 + lane]);
        float w[8];
#pragma unroll
        for (int q = 0; q < 8; q++) w[q] = wgt(as[q], ad);
        acc4(a0, w[0], r[0]); d0 += w[0];
        acc4(a1, w[1], r[1]); d1 += w[1];
        acc4(a2, w[2], r[2]); d2 += w[2];
        acc4(a3, w[3], r[3]); d3 += w[3];
        acc4(a0, w[4], r[4]); d0 += w[4];
        acc4(a1, w[5], r[5]); d1 += w[5];
        acc4(a2, w[6], r[6]); d2 += w[6];
        acc4(a3, w[7], r[7]); d3 += w[7];
    }
    for (; j + 1 < end; j += 2) {
        int s0 = __ldg(&g_src[j]), s1 = __ldg(&g_src[j + 1]);
        float x0 = __ldg(&g_as[s0 * HEADS + head]);
        float x1 = __ldg(&g_as[s1 * HEADS + head]);
        uint2 r0 = __ldg(&H[s0 * 32 + lane]);
        uint2 r1 = __ldg(&H[s1 * 32 + lane]);
        float w0 = wgt(x0, ad), w1 = wgt(x1, ad);
        acc4(a0, w0, r0); d0 += w0;
        acc4(a1, w1, r1); d1 += w1;
    }
    if (j < end) {
        int s0 = __ldg(&g_src[j]);
        float w0 = wgt(__ldg(&g_as[s0 * HEADS + head]), ad);
        acc4(a0, w0, __ldg(&H[s0 * 32 + lane]));
        d0 += w0;
    }

    float den = (d0 + d1) + (d2 + d3);
    float4 acc = make_float4((a0.x + a1.x) + (a2.x + a3.x),
                             (a0.y + a1.y) + (a2.y + a3.y),
                             (a0.z + a1.z) + (a2.z + a3.z),
                             (a0.w + a1.w) + (a2.w + a3.w));

    float inv = 1.f / (den + 1e-16f);
    float4 b4 = ((const float4*)bias)[lane];
    float4 v;
    v.x = acc.x * inv + b4.x;
    v.y = acc.y * inv + b4.y;
    v.z = acc.z * inv + b4.z;
    v.w = acc.w * inv + b4.w;

    float s  = v.x + v.y + v.z + v.w;
    float sq = v.x * v.x + v.y * v.y + v.z * v.z + v.w * v.w;
#pragma unroll
    for (int off = 16; off >= 1; off >>= 1) {
        s  += __shfl_xor_sync(0xffffffffu, s, off);
        sq += __shfl_xor_sync(0xffffffffu, sq, off);
    }
    float mu   = s * (1.f / 128.f);
    float var  = sq * (1.f / 128.f) - mu * mu;
    float rstd = rsqrtf(var + 1e-5f);

    float4 g4 = ((const float4*)gamma)[lane];
    float4 e4 = ((const float4*)beta)[lane];
    float t;
    t = (v.x - mu) * rstd * g4.x + e4.x; v.x = 0.5f * t * (1.f + erff(t * 0.70710678118f));
    t = (v.y - mu) * rstd * g4.y + e4.y; v.y = 0.5f * t * (1.f + erff(t * 0.70710678118f));
    t = (v.z - mu) * rstd * g4.z + e4.z; v.z = 0.5f * t * (1.f + erff(t * 0.70710678118f));
    t = (v.w - mu) * rstd * g4.w + e4.w; v.w = 0.5f * t * (1.f + erff(t * 0.70710678118f));
    ((float4*)out)[n * 32 + lane] = v;
}

extern "C" void kernel_launch(void* const* d_in, const int* in_sizes, int n_in,
                              void* d_out, int out_size)
{
    const float* x     = (const float*)d_in[0];
    const void*  ei    = d_in[1];
    const float* W     = (const float*)d_in[2];
    const float* att_s = (const float*)d_in[3];
    const float* att_d = (const float*)d_in[4];
    const float* bias  = (const float*)d_in[5];
    const float* gamma = (const float*)d_in[6];
    const float* beta  = (const float*)d_in[7];
    float* out = (float*)d_out;

    static cudaStream_t sB = nullptr;
    static cudaEvent_t evFork = nullptr, evJoin = nullptr;
    if (sB == nullptr) {
        cudaStreamCreateWithFlags(&sB, cudaStreamNonBlocking);
        cudaEventCreateWithFlags(&evFork, cudaEventDisableTiming);
        cudaEventCreateWithFlags(&evJoin, cudaEventDisableTiming);
    }

    // fork: stream B builds CSR while capture stream runs the GEMM
    cudaEventRecord(evFork, 0);
    cudaStreamWaitEvent(sB, evFork, 0);

    k_prep<<<(NPAD + 255) / 256, 256, 0, sB>>>((const unsigned*)ei);
    k_hist<<<(N_EDGES / 4 + 255) / 256, 256, 0, sB>>>(ei);
    k_scan<<<SCAN_B, 1024, 0, sB>>>();
    k_scatter<<<(N_EDGES / 4 + 255) / 256, 256, 0, sB>>>(ei);

    k_gemm<<<(N_NODES / 4 * 32 + 255) / 256, 256>>>(x, W, att_s, att_d);

    cudaEventRecord(evJoin, sB);
    cudaStreamWaitEvent(0, evJoin, 0);

    k_agg<<<(N_NODES * 32 + 255) / 256, 256>>>(out, bias, gamma, beta);
}

// round 8
// speedup vs baseline: 2.2210x; 1.0722x over previous
#include <cuda_runtime.h>
#include <cuda_fp16.h>
#include <math.h>

#define N_NODES 50000
#define N_EDGES 800000
#define HEADS   4
#define DIM     128
#define NPAD    50176            // 49 * 1024
#define SCAN_B  49

// -------- persistent scratch --------
__device__ __half   g_h16[N_NODES * DIM];     // 12.8 MB projected features (fp16)
__device__ float    g_as[N_NODES * HEADS];
__device__ float    g_ad[N_NODES * HEADS];
__device__ int      g_cnt[NPAD];
__device__ int      g_offs[NPAD];
__device__ int      g_cursor[NPAD];
__device__ int      g_bsum[SCAN_B];
__device__ int      g_arrive;
__device__ int      g_src[N_EDGES];
__device__ int      g_is64;

// ---- packed f32x2 helpers (Blackwell FFMA2 path) ----
__device__ __forceinline__ unsigned long long pack2(float a, float b) {
    unsigned long long r;
    asm("mov.b64 %0, {%1, %2};" : "=l"(r) : "f"(a), "f"(b));
    return r;
}
__device__ __forceinline__ void fma2(unsigned long long& d,
                                     unsigned long long a, unsigned long long b) {
    asm("fma.rn.f32x2 %0, %1, %2, %0;" : "+l"(d) : "l"(a), "l"(b));
}
__device__ __forceinline__ float2 unpack2(unsigned long long v) {
    float2 f;
    asm("mov.b64 {%0, %1}, %2;" : "=f"(f.x), "=f"(f.y) : "l"(v));
    return f;
}

// ---------------- prep: zero counters + reset scan counter + dtype detect ----------------
__global__ void k_prep(const unsigned* __restrict__ ei32) {
    int i = blockIdx.x * blockDim.x + threadIdx.x;
    if (i < NPAD) g_cnt[i] = 0;
    if (i == 0) {
        g_arrive = 0;
        int all_hi_zero = 1;
        for (int k = 0; k < 32; k++)
            if (ei32[2 * k + 1] != 0u) { all_hi_zero = 0; break; }
        g_is64 = all_hi_zero;
    }
}

// ---------------- histogram of dst (8 edges / thread) ----------------
__global__ __launch_bounds__(256) void k_hist(const void* __restrict__ ei) {
    int i = blockIdx.x * blockDim.x + threadIdx.x;
    if (i >= N_EDGES / 8) return;
    int d[8];
    if (g_is64) {
        const longlong2* p = (const longlong2*)((const long long*)ei + N_EDGES);
#pragma unroll
        for (int q = 0; q < 4; q++) {
            longlong2 v = p[4 * i + q];
            d[2 * q] = (int)v.x; d[2 * q + 1] = (int)v.y;
        }
    } else {
        const int4* p = (const int4*)((const int*)ei + N_EDGES);
        int4 a = p[2 * i], b = p[2 * i + 1];
        d[0] = a.x; d[1] = a.y; d[2] = a.z; d[3] = a.w;
        d[4] = b.x; d[5] = b.y; d[6] = b.z; d[7] = b.w;
    }
#pragma unroll
    for (int q = 0; q < 8; q++) atomicAdd(&g_cnt[d[q]], 1);
}

// ---------------- single-kernel exclusive scan (49 co-resident blocks) ----------------
__global__ __launch_bounds__(1024) void k_scan() {
    __shared__ int s[1024];
    __shared__ int pref;
    int t = threadIdx.x, b = blockIdx.x;
    int i = b * 1024 + t;
    int v = g_cnt[i];
    s[t] = v; __syncthreads();
#pragma unroll
    for (int off = 1; off < 1024; off <<= 1) {
        int x = (t >= off) ? s[t - off] : 0;
        __syncthreads();
        s[t] += x;
        __syncthreads();
    }
    int excl = s[t] - v;
    if (t == 1023) {
        g_bsum[b] = s[t];
        __threadfence();
        atomicAdd(&g_arrive, 1);
    }
    if (t == 0) {
        while (atomicAdd(&g_arrive, 0) < SCAN_B) { }
        int a = 0;
        for (int k = 0; k < b; k++) a += g_bsum[k];
        pref = a;
    }
    __syncthreads();
    int o = excl + pref;
    g_offs[i] = o;
    g_cursor[i] = o;
}

// ---------------- scatter: 8 edges / thread ----------------
__global__ __launch_bounds__(256) void k_scatter(const void* __restrict__ ei) {
    int i = blockIdx.x * blockDim.x + threadIdx.x;
    if (i >= N_EDGES / 8) return;
    int s[8], d[8];
    if (g_is64) {
        const longlong2* ps = (const longlong2*)ei;
        const longlong2* pd = (const longlong2*)((const long long*)ei + N_EDGES);
#pragma unroll
        for (int q = 0; q < 4; q++) {
            longlong2 vs = ps[4 * i + q];
            longlong2 vd = pd[4 * i + q];
            s[2 * q] = (int)vs.x; s[2 * q + 1] = (int)vs.y;
            d[2 * q] = (int)vd.x; d[2 * q + 1] = (int)vd.y;
        }
    } else {
        int4 sa = ((const int4*)ei)[2 * i], sb = ((const int4*)ei)[2 * i + 1];
        const int4* pd = (const int4*)((const int*)ei + N_EDGES);
        int4 da = pd[2 * i], db = pd[2 * i + 1];
        s[0] = sa.x; s[1] = sa.y; s[2] = sa.z; s[3] = sa.w;
        s[4] = sb.x; s[5] = sb.y; s[6] = sb.z; s[7] = sb.w;
        d[0] = da.x; d[1] = da.y; d[2] = da.z; d[3] = da.w;
        d[4] = db.x; d[5] = db.y; d[6] = db.z; d[7] = db.w;
    }
    int p[8];
#pragma unroll
    for (int q = 0; q < 8; q++) p[q] = atomicAdd(&g_cursor[d[q]], 1);
#pragma unroll
    for (int q = 0; q < 8; q++) g_src[p[q]] = s[q];
}

// ---------------- gemm: 4 nodes per warp, packed f32x2 FMA ----------------
__global__ __launch_bounds__(256) void k_gemm(
    const float* __restrict__ x, const float* __restrict__ W,
    const float* __restrict__ att_s, const float* __restrict__ att_d)
{
    int warp = (blockIdx.x * blockDim.x + threadIdx.x) >> 5;
    int lane = threadIdx.x & 31;
    int n0 = warp * 4;
    if (n0 >= N_NODES) return;     // N_NODES % 4 == 0

    float xv[4][4];
#pragma unroll
    for (int i = 0; i < 4; i++) {
        const float* xr = x + (n0 + i) * DIM;
#pragma unroll
        for (int j = 0; j < 4; j++) xv[i][j] = xr[j * 32 + lane];
    }

    unsigned long long accA[4], accB[4];
#pragma unroll
    for (int i = 0; i < 4; i++) { accA[i] = pack2(0.f, 0.f); accB[i] = pack2(0.f, 0.f); }

    const float4* W4 = (const float4*)W;
#pragma unroll 4
    for (int k = 0; k < 128; k++) {
        float4 w = W4[k * 32 + lane];
        unsigned long long wA = pack2(w.x, w.y);
        unsigned long long wB = pack2(w.z, w.w);
#pragma unroll
        for (int i = 0; i < 4; i++) {
            float xk = __shfl_sync(0xffffffffu, xv[i][k >> 5], k & 31);
            unsigned long long xx = pack2(xk, xk);
            fma2(accA[i], xx, wA);
            fma2(accB[i], xx, wB);
        }
    }

    int head = lane >> 3;
    int base = head * 32 + (lane & 7) * 4;
    float as0 = att_s[base + 0], as1 = att_s[base + 1],
          as2 = att_s[base + 2], as3 = att_s[base + 3];
    float ad0 = att_d[base + 0], ad1 = att_d[base + 1],
          ad2 = att_d[base + 2], ad3 = att_d[base + 3];

#pragma unroll
    for (int i = 0; i < 4; i++) {
        int n = n0 + i;
        float2 lo = unpack2(accA[i]);
        float2 hi = unpack2(accB[i]);
        __half2 h0 = __floats2half2_rn(lo.x, lo.y);
        __half2 h1 = __floats2half2_rn(hi.x, hi.y);
        uint2 pk;
        pk.x = *(unsigned*)&h0;
        pk.y = *(unsigned*)&h1;
        ((uint2*)g_h16)[n * 32 + lane] = pk;

        float s = lo.x * as0 + lo.y * as1 + hi.x * as2 + hi.y * as3;
        float d = lo.x * ad0 + lo.y * ad1 + hi.x * ad2 + hi.y * ad3;
#pragma unroll
        for (int off = 4; off >= 1; off >>= 1) {
            s += __shfl_xor_sync(0xffffffffu, s, off);
            d += __shfl_xor_sync(0xffffffffu, d, off);
        }
        if ((lane & 7) == 0) {
            g_as[n * HEADS + head] = s;
            g_ad[n * HEADS + head] = d;
        }
    }
}

// ---------------- fused aggregate + softmax + bias + LN + GELU ----------------
// warp per node; exp computed once per (edge,head): lane l owns edge l>>2, head l&3.
__global__ __launch_bounds__(256) void k_agg(
    float* __restrict__ out, const float* __restrict__ bias,
    const float* __restrict__ gamma, const float* __restrict__ beta)
{
    int n = (blockIdx.x * blockDim.x + threadIdx.x) >> 5;
    int lane = threadIdx.x & 31;
    if (n >= N_NODES) return;
    int head = lane >> 3;            // column-group head (accumulation)
    int hm   = lane & 3;             // head this lane computes exp for
    int eq   = lane >> 2;            // edge slot this lane computes exp for (0..7)
    int idx0 = lane & 7;             // src-load slot

    float ad_e = __ldg(&g_ad[n * HEADS + hm]);

    int start = g_offs[n];
    int deg   = g_offs[n + 1] - start;
    int cnt   = deg + 1;             // + self loop

    const uint2* H = (const uint2*)g_h16;

    unsigned long long aA[4], aB[4];
#pragma unroll
    for (int q = 0; q < 4; q++) { aA[q] = pack2(0.f, 0.f); aB[q] = pack2(0.f, 0.f); }
    float den[4] = {0.f, 0.f, 0.f, 0.f};

    // prefetch src vector for iteration 0 (idx==deg -> self, idx>deg -> pad=self)
    int srcv_next = (idx0 < deg) ? __ldg(&g_src[start + idx0]) : n;

    for (int base = 0; base < cnt; base += 8) {
        int srcv = srcv_next;
        int nb = base + 8;
        if (nb < cnt) {
            int idx = nb + idx0;
            srcv_next = (idx < deg) ? __ldg(&g_src[start + idx]) : n;
        }
        // --- exp duty: one (edge, head) pair per lane ---
        int   se   = __shfl_sync(0xffffffffu, srcv, eq);
        float as_e = __ldg(&g_as[se * HEADS + hm]);
        float e = as_e + ad_e;
        e = (e < 0.f) ? 0.2f * e : e;
        float w_l = ((base + eq) < cnt) ? __expf(e) : 0.f;

        // --- accumulate 8 edges ---
#pragma unroll
        for (int q = 0; q < 8; q++) {
            int   sq = __shfl_sync(0xffffffffu, srcv, q);
            float wq = __shfl_sync(0xffffffffu, w_l, q * 4 + head);
            uint2 r  = __ldg(&H[sq * 32 + lane]);
            float2 lo = __half22float2(*(__half2*)&r.x);
            float2 hi = __half22float2(*(__half2*)&r.y);
            unsigned long long ww = pack2(wq, wq);
            fma2(aA[q & 3], ww, pack2(lo.x, lo.y));
            fma2(aB[q & 3], ww, pack2(hi.x, hi.y));
            den[q & 3] += wq;
        }
    }

    float dtot = (den[0] + den[1]) + (den[2] + den[3]);
    float2 A0 = unpack2(aA[0]), A1 = unpack2(aA[1]), A2 = unpack2(aA[2]), A3 = unpack2(aA[3]);
    float2 B0 = unpack2(aB[0]), B1 = unpack2(aB[1]), B2 = unpack2(aB[2]), B3 = unpack2(aB[3]);
    float4 acc;
    acc.x = (A0.x + A1.x) + (A2.x + A3.x);
    acc.y = (A0.y + A1.y) + (A2.y + A3.y);
    acc.z = (B0.x + B1.x) + (B2.x + B3.x);
    acc.w = (B0.y + B1.y) + (B2.y + B3.y);

    float inv = 1.f / (dtot + 1e-16f);
    float4 b4 = ((const float4*)bias)[lane];
    float4 v;
    v.x = acc.x * inv + b4.x;
    v.y = acc.y * inv + b4.y;
    v.z = acc.z * inv + b4.z;
    v.w = acc.w * inv + b4.w;

    float s  = v.x + v.y + v.z + v.w;
    float sq = v.x * v.x + v.y * v.y + v.z * v.z + v.w * v.w;
#pragma unroll
    for (int off = 16; off >= 1; off >>= 1) {
        s  += __shfl_xor_sync(0xffffffffu, s, off);
        sq += __shfl_xor_sync(0xffffffffu, sq, off);
    }
    float mu   = s * (1.f / 128.f);
    float var  = sq * (1.f / 128.f) - mu * mu;
    float rstd = rsqrtf(var + 1e-5f);

    float4 g4 = ((const float4*)gamma)[lane];
    float4 e4 = ((const float4*)beta)[lane];
    float t;
    t = (v.x - mu) * rstd * g4.x + e4.x; v.x = 0.5f * t * (1.f + erff(t * 0.70710678118f));
    t = (v.y - mu) * rstd * g4.y + e4.y; v.y = 0.5f * t * (1.f + erff(t * 0.70710678118f));
    t = (v.z - mu) * rstd * g4.z + e4.z; v.z = 0.5f * t * (1.f + erff(t * 0.70710678118f));
    t = (v.w - mu) * rstd * g4.w + e4.w; v.w = 0.5f * t * (1.f + erff(t * 0.70710678118f));
    ((float4*)out)[n * 32 + lane] = v;
}

extern "C" void kernel_launch(void* const* d_in, const int* in_sizes, int n_in,
                              void* d_out, int out_size)
{
    const float* x     = (const float*)d_in[0];
    const void*  ei    = d_in[1];
    const float* W     = (const float*)d_in[2];
    const float* att_s = (const float*)d_in[3];
    const float* att_d = (const float*)d_in[4];
    const float* bias  = (const float*)d_in[5];
    const float* gamma = (const float*)d_in[6];
    const float* beta  = (const float*)d_in[7];
    float* out = (float*)d_out;

    static cudaStream_t sB = nullptr;
    static cudaEvent_t evFork = nullptr, evJoin = nullptr;
    if (sB == nullptr) {
        cudaStreamCreateWithFlags(&sB, cudaStreamNonBlocking);
        cudaEventCreateWithFlags(&evFork, cudaEventDisableTiming);
        cudaEventCreateWithFlags(&evJoin, cudaEventDisableTiming);
    }

    // fork: stream B builds CSR while capture stream runs the GEMM
    cudaEventRecord(evFork, 0);
    cudaStreamWaitEvent(sB, evFork, 0);

    k_prep<<<(NPAD + 255) / 256, 256, 0, sB>>>((const unsigned*)ei);
    k_hist<<<(N_EDGES / 8 + 255) / 256, 256, 0, sB>>>(ei);
    k_scan<<<SCAN_B, 1024, 0, sB>>>();
    k_scatter<<<(N_EDGES / 8 + 255) / 256, 256, 0, sB>>>(ei);

    k_gemm<<<(N_NODES / 4 * 32 + 255) / 256, 256>>>(x, W, att_s, att_d);

    cudaEventRecord(evJoin, sB);
    cudaStreamWaitEvent(0, evJoin, 0);

    k_agg<<<(N_NODES * 32 + 255) / 256, 256>>>(out, bias, gamma, beta);
}